// round 2
// baseline (speedup 1.0000x reference)
#include <cuda_runtime.h>
#include <cstdint>

// -------------------------------------------------------------------------
// SimpleESN on B200: persistent cooperative kernel.
//   - W (2048x2048 fp32, 16.8MB) distributed across 128 CTAs' shared memory,
//     loaded once, reused for all 2048 timesteps.
//   - Each step: every CTA computes 16 output columns for all 16 batches
//     (h @ W slice) using packed fma.rn.f32x2, plus the input projection
//     x_t @ kernel slice on the fly, tanh, store h slice, grid barrier.
//   - h ping-pongs between two __device__ buffers; grid barrier is a
//     replay-safe epoch barrier (base epoch read at kernel start).
// -------------------------------------------------------------------------

namespace {
constexpr int B_      = 16;
constexpr int T_      = 2048;
constexpr int F_      = 128;
constexpr int U_      = 2048;
constexpr int GRID    = 128;
constexpr int THREADS = 256;
constexpr int COLS    = U_ / GRID;     // 16 columns per CTA
constexpr int CHUNK   = 512;           // k's staged per smem chunk
constexpr int NCHUNK  = U_ / CHUNK;    // 4
constexpr int KG      = THREADS / COLS;// 16 k-groups
constexpr int KPT     = CHUNK / KG;    // 32 k per thread per chunk
}

// h state ping-pong buffers, layout [n][b] (b contiguous, 16 per row)
__device__ __align__(16) float g_h[2][U_ * B_];
// grid barrier state (monotonic across graph replays; base-relative)
__device__ unsigned g_arrive = 0;
__device__ unsigned g_epoch  = 0;

struct SmemLayout {
  float Ws[U_ * COLS];               // 131072 B  W slice, [k][c]
  float Ks[F_ * COLS];               //   8192 B  input-kernel slice, [f][c]
  float hs[CHUNK * B_];              //  32768 B  staged h chunk, [k][b]
  float xs[B_ * 132];                //   8448 B  x_t rows, padded to 132
  unsigned long long red[KG * 144];  //  18432 B  partial sums (padded, f32x2)
  float bias_s[COLS];
  float wout_s[COLS];
  float ybuf[COLS * B_];
};

__device__ __forceinline__ unsigned ld_acq(unsigned* p) {
  unsigned v;
  asm volatile("ld.acquire.gpu.global.u32 %0, [%1];" : "=r"(v) : "l"(p) : "memory");
  return v;
}
__device__ __forceinline__ void st_rel(unsigned* p, unsigned v) {
  asm volatile("st.release.gpu.global.u32 [%0], %1;" :: "l"(p), "r"(v) : "memory");
}

__global__ void __launch_bounds__(THREADS, 1) esn_kernel(
    const float* __restrict__ x,     // [B,T,F]
    const float* __restrict__ kern,  // [F,U]
    const float* __restrict__ W,     // [U,U]
    const float* __restrict__ bias,  // [U]
    const float* __restrict__ wout,  // [U,1]
    const float* __restrict__ bout,  // [1]
    float* __restrict__ out)         // [B,1]
{
  extern __shared__ unsigned char smem_raw[];
  SmemLayout& s = *reinterpret_cast<SmemLayout*>(smem_raw);
  const int tid = threadIdx.x;
  const int n0  = blockIdx.x * COLS;

  // main-dot mapping: column + k-group
  const int cM = tid & (COLS - 1);
  const int kg = tid >> 4;
  // u / store / reduce mapping: (column, batch)
  const int cS = tid >> 4;
  const int bS = tid & (B_ - 1);

  unsigned epoch_base = 0;
  if (tid == 0) epoch_base = ld_acq(&g_epoch);  // stable at launch

  // init output with b_out; atomics accumulate partial readouts at the end
  if (blockIdx.x == 0 && tid < B_) out[tid] = bout[0];

  // ---- load persistent W / kernel slices into smem (once) ----
  for (int i = tid; i < U_ * COLS; i += THREADS) {
    int k = i >> 4, c = i & (COLS - 1);
    s.Ws[i] = W[k * U_ + n0 + c];
  }
  for (int i = tid; i < F_ * COLS; i += THREADS) {
    int f = i >> 4, c = i & (COLS - 1);
    s.Ks[i] = kern[f * U_ + n0 + c];
  }
  if (tid < COLS) {
    s.bias_s[tid] = bias[n0 + tid];
    s.wout_s[tid] = wout[n0 + tid];
  }
  __syncthreads();

  unsigned bar_target = 0;
  float hval = 0.f;

  for (int t = 0; t < T_; ++t) {
    // ---- stage x_t (16 rows x 128 floats, padded rows of 132) ----
    for (int i = tid; i < B_ * (F_ / 4); i += THREADS) {
      int b = i >> 5, fq = i & 31;
      float4 v = *reinterpret_cast<const float4*>(&x[(b * T_ + t) * F_ + fq * 4]);
      *reinterpret_cast<float4*>(&s.xs[b * 132 + fq * 4]) = v;
    }

    float dot = 0.f;
    if (t == 0) {
      __syncthreads();  // publish xs
    } else {
      const float4* hsrc = reinterpret_cast<const float4*>(g_h[(t - 1) & 1]);

      unsigned long long acc[8];
      #pragma unroll
      for (int j = 0; j < 8; ++j) acc[j] = 0ull;

      // register-prefetch chunk 0 (overlaps with xs staging above)
      float4 pf[8];
      #pragma unroll
      for (int j = 0; j < 8; ++j) pf[j] = hsrc[tid + j * THREADS];

      for (int ch = 0; ch < NCHUNK; ++ch) {
        // commit prefetched chunk to smem, then prefetch next (latency
        // hidden under this chunk's compute)
        #pragma unroll
        for (int j = 0; j < 8; ++j)
          reinterpret_cast<float4*>(s.hs)[tid + j * THREADS] = pf[j];
        if (ch + 1 < NCHUNK) {
          #pragma unroll
          for (int j = 0; j < 8; ++j)
            pf[j] = hsrc[(ch + 1) * (CHUNK * B_ / 4) + tid + j * THREADS];
        }
        __syncthreads();

        const float* Wp = &s.Ws[(ch * CHUNK) * COLS + cM];
        #pragma unroll 8
        for (int i = 0; i < KPT; ++i) {
          const int kl = kg * KPT + i;
          const ulonglong2* hrow =
              reinterpret_cast<const ulonglong2*>(&s.hs[kl * B_]);
          ulonglong2 hA = hrow[0];
          ulonglong2 hB = hrow[1];
          float w = Wp[kl * COLS];
          unsigned wb = __float_as_uint(w);
          unsigned long long w2;
          asm("mov.b64 %0, {%1, %1};" : "=l"(w2) : "r"(wb));
          asm("fma.rn.f32x2 %0, %1, %2, %0;" : "+l"(acc[0]) : "l"(hA.x), "l"(w2));
          asm("fma.rn.f32x2 %0, %1, %2, %0;" : "+l"(acc[1]) : "l"(hA.y), "l"(w2));
          asm("fma.rn.f32x2 %0, %1, %2, %0;" : "+l"(acc[2]) : "l"(hB.x), "l"(w2));
          asm("fma.rn.f32x2 %0, %1, %2, %0;" : "+l"(acc[3]) : "l"(hB.y), "l"(w2));
          ulonglong2 hC = hrow[2];
          ulonglong2 hD = hrow[3];
          asm("fma.rn.f32x2 %0, %1, %2, %0;" : "+l"(acc[4]) : "l"(hC.x), "l"(w2));
          asm("fma.rn.f32x2 %0, %1, %2, %0;" : "+l"(acc[5]) : "l"(hC.y), "l"(w2));
          asm("fma.rn.f32x2 %0, %1, %2, %0;" : "+l"(acc[6]) : "l"(hD.x), "l"(w2));
          asm("fma.rn.f32x2 %0, %1, %2, %0;" : "+l"(acc[7]) : "l"(hD.y), "l"(w2));
        }
        __syncthreads();
      }

      // cross-k-group reduction (padded u64 layout: conflict-free stores)
      #pragma unroll
      for (int j = 0; j < 8; ++j) s.red[kg * 144 + cM * 9 + j] = acc[j];
      __syncthreads();
      const float* redf = reinterpret_cast<const float*>(s.red);
      float sum = 0.f;
      #pragma unroll
      for (int g2 = 0; g2 < KG; ++g2) sum += redf[g2 * 288 + cS * 18 + bS];
      dot = sum;
    }

    // ---- input projection u = bias + x_t . kernel[:, n0+cS] ----
    float u = s.bias_s[cS];
    {
      const float* xrow = &s.xs[bS * 132];
      const float* kcol = &s.Ks[cS];
      #pragma unroll 16
      for (int f = 0; f < F_; ++f) u += xrow[f] * kcol[f * COLS];
    }
    hval = tanhf(u + dot);
    g_h[t & 1][(n0 + cS) * B_ + bS] = hval;

    // ---- grid barrier (epoch-based, replay-safe) ----
    __threadfence();
    __syncthreads();
    if (tid == 0) {
      ++bar_target;
      if (atomicAdd(&g_arrive, 1u) == GRID - 1) {
        g_arrive = 0;
        __threadfence();
        st_rel(&g_epoch, epoch_base + bar_target);
      } else {
        while ((int)(ld_acq(&g_epoch) - (epoch_base + bar_target)) < 0) {}
      }
    }
    __syncthreads();
  }

  // ---- readout: out[b] = b_out + sum_n h[b,n]*w_out[n] ----
  s.ybuf[cS * B_ + bS] = hval * s.wout_s[cS];
  __syncthreads();
  if (tid < B_) {
    float y = 0.f;
    #pragma unroll
    for (int c = 0; c < COLS; ++c) y += s.ybuf[c * B_ + tid];
    atomicAdd(&out[tid], y);
  }
}

extern "C" void kernel_launch(void* const* d_in, const int* in_sizes, int n_in,
                              void* d_out, int out_size) {
  (void)in_sizes; (void)n_in; (void)out_size;
  const float* x    = (const float*)d_in[0];
  const float* kern = (const float*)d_in[1];
  const float* W    = (const float*)d_in[2];
  const float* bias = (const float*)d_in[3];
  const float* wout = (const float*)d_in[4];
  const float* bout = (const float*)d_in[5];

  cudaFuncSetAttribute(esn_kernel, cudaFuncAttributeMaxDynamicSharedMemorySize,
                       (int)sizeof(SmemLayout));
  esn_kernel<<<GRID, THREADS, sizeof(SmemLayout)>>>(
      x, kern, W, bias, wout, bout, (float*)d_out);
}

// round 3
// speedup vs baseline: 1.0797x; 1.0797x over previous
#include <cuda_runtime.h>
#include <cstdint>

// -------------------------------------------------------------------------
// SimpleESN persistent cooperative kernel, round 2.
//  - 128 CTAs x 512 threads, occupancy 1 CTA/SM.
//  - W slice (2048x16) resident in smem with row stride 17 (bank-conflict-
//    free w loads across the two k-groups of each warp).
//  - 32 k-groups x 16 cols; packed fma.rn.f32x2 over 16 batches.
//  - Warp-shuffle (xor 16) pre-reduction, then smem reduction.
//  - Epoch grid barrier polled by every thread (acquire loads); input
//    projection u_{t+1} computed after arrival, x staged under compute.
// -------------------------------------------------------------------------

namespace {
constexpr int B_      = 16;
constexpr int T_      = 2048;
constexpr int F_      = 128;
constexpr int U_      = 2048;
constexpr int GRID    = 128;
constexpr int THREADS = 512;
constexpr int COLS    = 16;             // output columns per CTA
constexpr int CHUNK   = 512;            // k staged per smem chunk
constexpr int NCHUNK  = U_ / CHUNK;     // 4
constexpr int KG      = THREADS / COLS; // 32 k-groups
constexpr int KPT     = CHUNK / KG;     // 16 k per thread per chunk
constexpr int WROW    = 17;             // padded Ws row stride (floats)
constexpr int XSR     = 132;            // padded x row stride
constexpr int REDROW  = 145;            // u64 per reduction row (16*9+1)
}

__device__ __align__(16) float g_h[2][U_ * B_];
__device__ unsigned g_arrive = 0;
__device__ unsigned g_epoch  = 0;

struct SmemLayout {
  float Ws[U_ * WROW];                       // 139264 B  [k][c], stride 17
  float Ks[F_ * COLS];                       //   8192 B  [f][c]
  float hs[CHUNK * B_];                      //  32768 B  [k][b]
  float xs[2][B_ * XSR];                     //  16896 B
  unsigned long long red[(KG / 2) * REDROW]; //  18560 B
  float bias_s[COLS];
  float wout_s[COLS];
  float ybuf[COLS * B_];
};
static_assert(sizeof(SmemLayout) <= 227 * 1024, "smem");

__device__ __forceinline__ unsigned ld_acq(unsigned* p) {
  unsigned v;
  asm volatile("ld.acquire.gpu.global.u32 %0, [%1];" : "=r"(v) : "l"(p) : "memory");
  return v;
}
__device__ __forceinline__ void st_rel(unsigned* p, unsigned v) {
  asm volatile("st.release.gpu.global.u32 [%0], %1;" :: "l"(p), "r"(v) : "memory");
}
__device__ __forceinline__ unsigned long long f32x2_add(unsigned long long a,
                                                        unsigned long long b) {
  unsigned long long r;
  asm("add.rn.f32x2 %0, %1, %2;" : "=l"(r) : "l"(a), "l"(b));
  return r;
}

__global__ void __launch_bounds__(THREADS, 1) esn_kernel(
    const float* __restrict__ x,     // [B,T,F]
    const float* __restrict__ kern,  // [F,U]
    const float* __restrict__ W,     // [U,U]
    const float* __restrict__ bias,  // [U]
    const float* __restrict__ wout,  // [U,1]
    const float* __restrict__ bout,  // [1]
    float* __restrict__ out)         // [B,1]
{
  extern __shared__ unsigned char smem_raw[];
  SmemLayout& s = *reinterpret_cast<SmemLayout*>(smem_raw);
  const int tid  = threadIdx.x;
  const int n0   = blockIdx.x * COLS;
  const int cM   = tid & (COLS - 1);   // column (main dot)
  const int kg   = tid >> 4;           // k-group 0..31
  const int wrp  = tid >> 5;           // warp id 0..15
  const int lane = tid & 31;
  const int cS   = (tid >> 4) & 15;    // column (u / store), valid tid<256
  const int bS   = tid & (B_ - 1);     // batch

  const unsigned epoch_base = ld_acq(&g_epoch);  // stable at launch

  if (blockIdx.x == 0 && tid < B_) out[tid] = bout[0];

  // ---- persistent smem loads (once) ----
  for (int i = tid; i < U_ * COLS; i += THREADS) {
    int k = i >> 4, c = i & (COLS - 1);
    s.Ws[k * WROW + c] = W[k * U_ + n0 + c];
  }
  for (int i = tid; i < F_ * COLS; i += THREADS) {
    int f = i >> 4, c = i & (COLS - 1);
    s.Ks[i] = kern[f * U_ + n0 + c];
  }
  if (tid < COLS) {
    s.bias_s[tid] = bias[n0 + tid];
    s.wout_s[tid] = wout[n0 + tid];
  }

  // stage x_0, then compute u_0
  {
    int b = tid >> 5, fq = tid & 31;
    *reinterpret_cast<float4*>(&s.xs[0][b * XSR + fq * 4]) =
        *reinterpret_cast<const float4*>(&x[(b * T_ + 0) * F_ + fq * 4]);
  }
  __syncthreads();

  float u = 0.f;
  if (tid < 256) {
    u = s.bias_s[cS];
    const float* xrow = &s.xs[0][bS * XSR];
    const float* kcol = &s.Ks[cS];
    #pragma unroll 8
    for (int f = 0; f < F_; ++f) u += xrow[f] * kcol[f * COLS];
  }

  float hval = 0.f;

  for (int t = 0; t < T_; ++t) {
    float dot = 0.f;

    if (t > 0) {
      // ---- wait for h[t-1] (every thread: per-thread acquire) ----
      const unsigned tgt = epoch_base + (unsigned)t;
      while ((int)(ld_acq(&g_epoch) - tgt) < 0) {}

      const float4* hsrc = reinterpret_cast<const float4*>(g_h[(t - 1) & 1]);
      float4 pf[4];
      #pragma unroll
      for (int j = 0; j < 4; ++j) pf[j] = hsrc[tid + j * THREADS];

      unsigned long long acc[8];
      #pragma unroll
      for (int j = 0; j < 8; ++j) acc[j] = 0ull;

      for (int ch = 0; ch < NCHUNK; ++ch) {
        #pragma unroll
        for (int j = 0; j < 4; ++j)
          reinterpret_cast<float4*>(s.hs)[tid + j * THREADS] = pf[j];
        if (ch + 1 < NCHUNK) {
          #pragma unroll
          for (int j = 0; j < 4; ++j)
            pf[j] = hsrc[(ch + 1) * (CHUNK * B_ / 4) + tid + j * THREADS];
        }
        __syncthreads();

        if (ch == 0 && t + 1 < T_) {
          // stage x_{t+1} under chunk-0 compute (safe: prior sync ordered
          // all u_t readers of the target buffer)
          int b = tid >> 5, fq = tid & 31;
          *reinterpret_cast<float4*>(&s.xs[(t + 1) & 1][b * XSR + fq * 4]) =
              *reinterpret_cast<const float4*>(&x[(b * T_ + t + 1) * F_ + fq * 4]);
        }

        #pragma unroll
        for (int i = 0; i < KPT; ++i) {
          const int kl = kg * KPT + i;
          const ulonglong2* hrow =
              reinterpret_cast<const ulonglong2*>(&s.hs[kl * B_]);
          ulonglong2 hA = hrow[0];
          ulonglong2 hB = hrow[1];
          float w = s.Ws[(ch * CHUNK + kl) * WROW + cM];
          unsigned wb = __float_as_uint(w);
          unsigned long long w2;
          asm("mov.b64 %0, {%1, %1};" : "=l"(w2) : "r"(wb));
          asm("fma.rn.f32x2 %0, %1, %2, %0;" : "+l"(acc[0]) : "l"(hA.x), "l"(w2));
          asm("fma.rn.f32x2 %0, %1, %2, %0;" : "+l"(acc[1]) : "l"(hA.y), "l"(w2));
          asm("fma.rn.f32x2 %0, %1, %2, %0;" : "+l"(acc[2]) : "l"(hB.x), "l"(w2));
          asm("fma.rn.f32x2 %0, %1, %2, %0;" : "+l"(acc[3]) : "l"(hB.y), "l"(w2));
          ulonglong2 hC = hrow[2];
          ulonglong2 hD = hrow[3];
          asm("fma.rn.f32x2 %0, %1, %2, %0;" : "+l"(acc[4]) : "l"(hC.x), "l"(w2));
          asm("fma.rn.f32x2 %0, %1, %2, %0;" : "+l"(acc[5]) : "l"(hC.y), "l"(w2));
          asm("fma.rn.f32x2 %0, %1, %2, %0;" : "+l"(acc[6]) : "l"(hD.x), "l"(w2));
          asm("fma.rn.f32x2 %0, %1, %2, %0;" : "+l"(acc[7]) : "l"(hD.y), "l"(w2));
        }
        __syncthreads();
      }

      // ---- warp pre-reduction: combine kg pairs (lanes l and l+16) ----
      #pragma unroll
      for (int j = 0; j < 8; ++j) {
        unsigned long long other = __shfl_xor_sync(0xFFFFFFFFu, acc[j], 16);
        acc[j] = f32x2_add(acc[j], other);
      }
      if (lane < 16) {
        #pragma unroll
        for (int j = 0; j < 8; ++j)
          s.red[wrp * REDROW + lane * 9 + j] = acc[j];
      }
      __syncthreads();

      if (tid < 256) {
        const float* redf = reinterpret_cast<const float*>(s.red);
        float sum = 0.f;
        #pragma unroll
        for (int g = 0; g < KG / 2; ++g)
          sum += redf[g * (REDROW * 2) + cS * 18 + bS];
        dot = sum;
      }
    } else {
      // t == 0: no h yet; stage x_1 into the other buffer
      if (t + 1 < T_) {
        int b = tid >> 5, fq = tid & 31;
        *reinterpret_cast<float4*>(&s.xs[1][b * XSR + fq * 4]) =
            *reinterpret_cast<const float4*>(&x[(b * T_ + 1) * F_ + fq * 4]);
      }
    }

    // ---- state update ----
    if (tid < 256) {
      hval = tanhf(u + dot);
      g_h[t & 1][(n0 + cS) * B_ + bS] = hval;
    }
    __threadfence();
    __syncthreads();
    if (tid == 0) {
      if (atomicAdd(&g_arrive, 1u) == GRID - 1) {
        g_arrive = 0;
        __threadfence();
        st_rel(&g_epoch, epoch_base + (unsigned)t + 1u);
      }
    }

    // ---- compute u_{t+1} while other CTAs arrive ----
    if (t + 1 < T_ && tid < 256) {
      u = s.bias_s[cS];
      const float* xrow = &s.xs[(t + 1) & 1][bS * XSR];
      const float* kcol = &s.Ks[cS];
      #pragma unroll 8
      for (int f = 0; f < F_; ++f) u += xrow[f] * kcol[f * COLS];
    }
  }

  // ---- readout: out[b] += sum_c h[b, n0+c] * w_out[n0+c] ----
  if (tid < 256) s.ybuf[cS * B_ + bS] = hval * s.wout_s[cS];
  __syncthreads();
  if (tid < B_) {
    float y = 0.f;
    #pragma unroll
    for (int c = 0; c < COLS; ++c) y += s.ybuf[c * B_ + tid];
    atomicAdd(&out[tid], y);
  }
}

extern "C" void kernel_launch(void* const* d_in, const int* in_sizes, int n_in,
                              void* d_out, int out_size) {
  (void)in_sizes; (void)n_in; (void)out_size;
  const float* x    = (const float*)d_in[0];
  const float* kern = (const float*)d_in[1];
  const float* W    = (const float*)d_in[2];
  const float* bias = (const float*)d_in[3];
  const float* wout = (const float*)d_in[4];
  const float* bout = (const float*)d_in[5];

  cudaFuncSetAttribute(esn_kernel, cudaFuncAttributeMaxDynamicSharedMemorySize,
                       (int)sizeof(SmemLayout));
  esn_kernel<<<GRID, THREADS, sizeof(SmemLayout)>>>(
      x, kern, W, bias, wout, bout, (float*)d_out);
}

// round 4
// speedup vs baseline: 1.4147x; 1.3103x over previous
#include <cuda_runtime.h>
#include <cstdint>

// -------------------------------------------------------------------------
// SimpleESN persistent cooperative kernel, round 3.
// Warp geometry: 8 col-pairs x 2 batch-halves x 2 k-groups (interleaved k)
//   -> all hs/Ws shared-memory accesses conflict-free with natural layouts.
// 2 cols/thread amortizes the h-row LDS; fma.rn.f32x2 over batch pairs.
// tid0-only epoch poll, acq_rel arrive atomic (no threadfence/CCTL.IVALL),
// h read via ld.global.cg (L1 bypass keeps ping-pong reads coherent).
// -------------------------------------------------------------------------

namespace {
constexpr int B_      = 16;
constexpr int T_      = 2048;
constexpr int F_      = 128;
constexpr int U_      = 2048;
constexpr int GRID    = 128;
constexpr int THREADS = 512;
constexpr int COLS    = 16;
constexpr int CHUNK   = 512;          // k per staged chunk
constexpr int NCHUNK  = U_ / CHUNK;   // 4
constexpr int IPC     = CHUNK / 32;   // 16 iterations per chunk (kl=i*32+kg)
constexpr int XSR     = 132;          // x row stride (floats)
constexpr int KSR     = 132;          // transposed-kernel row stride
constexpr int REDROW  = 288;          // floats per warp partial row (16c x 18)
}

__device__ __align__(16) float g_h[2][U_ * B_];
__device__ unsigned g_arrive = 0;
__device__ unsigned g_epoch  = 0;

struct SmemLayout {
  float Ws[U_ * COLS];        // 131072 B  [k][c], unpadded (conflict-free)
  float hs[CHUNK * B_];       //  32768 B  [k][b], unpadded (conflict-free)
  float red[16 * REDROW];     //  18432 B  warp partials [w][c][b], c-pad 18
  float xs[2][B_ * XSR];      //  16896 B  x_t rows
  float Kt[COLS * KSR];       //   8448 B  input kernel transposed [c][f]
  float bias_s[COLS];
  float wout_s[COLS];
  float ybuf[COLS * B_];
};
static_assert(sizeof(SmemLayout) <= 232448, "smem");

using u64 = unsigned long long;

__device__ __forceinline__ unsigned ld_acq(unsigned* p) {
  unsigned v;
  asm volatile("ld.acquire.gpu.global.u32 %0, [%1];" : "=r"(v) : "l"(p) : "memory");
  return v;
}
__device__ __forceinline__ void st_rel(unsigned* p, unsigned v) {
  asm volatile("st.release.gpu.global.u32 [%0], %1;" :: "l"(p), "r"(v) : "memory");
}
__device__ __forceinline__ unsigned atom_arrive(unsigned* p) {
  unsigned v;
  asm volatile("atom.acq_rel.gpu.global.add.u32 %0, [%1], 1;"
               : "=r"(v) : "l"(p) : "memory");
  return v;
}
__device__ __forceinline__ float4 ldcg4(const float4* p) {
  float4 v;
  asm volatile("ld.global.cg.v4.f32 {%0,%1,%2,%3}, [%4];"
               : "=f"(v.x), "=f"(v.y), "=f"(v.z), "=f"(v.w) : "l"(p));
  return v;
}
__device__ __forceinline__ u64 splat2(float w) {
  u64 r;
  asm("mov.b64 %0, {%1, %1};" : "=l"(r) : "r"(__float_as_uint(w)));
  return r;
}
__device__ __forceinline__ void fmax2(u64& a, u64 h, u64 w) {
  asm("fma.rn.f32x2 %0, %1, %2, %0;" : "+l"(a) : "l"(h), "l"(w));
}
__device__ __forceinline__ u64 addx2(u64 a, u64 b) {
  u64 r;
  asm("add.rn.f32x2 %0, %1, %2;" : "=l"(r) : "l"(a), "l"(b));
  return r;
}

__global__ void __launch_bounds__(THREADS, 1) esn_kernel(
    const float* __restrict__ x,     // [B,T,F]
    const float* __restrict__ kern,  // [F,U]
    const float* __restrict__ W,     // [U,U]
    const float* __restrict__ bias,  // [U]
    const float* __restrict__ wout,  // [U,1]
    const float* __restrict__ bout,  // [1]
    float* __restrict__ out)         // [B,1]
{
  extern __shared__ unsigned char smem_raw[];
  SmemLayout& s = *reinterpret_cast<SmemLayout*>(smem_raw);
  const int tid  = threadIdx.x;
  const int n0   = blockIdx.x * COLS;
  const int lane = tid & 31;
  const int wrp  = tid >> 5;                    // 0..15
  const int hf   = (lane >> 3) & 1;             // batch half
  const int p    = lane & 7;                    // col pair
  const int kg   = wrp * 2 + (lane >> 4);       // k-group 0..31
  const int cS   = (tid >> 4) & 15;             // output col (tid<256)
  const int bS   = tid & 15;                    // output batch

  unsigned epoch_base = 0;
  if (tid == 0) epoch_base = ld_acq(&g_epoch);

  if (blockIdx.x == 0 && tid < B_) out[tid] = bout[0];

  // ---- persistent smem loads (once) ----
  for (int i = tid; i < U_ * COLS; i += THREADS) {
    int k = i >> 4, c = i & 15;
    s.Ws[i] = W[k * U_ + n0 + c];
  }
  for (int i = tid; i < COLS * F_; i += THREADS) {
    int c = i >> 7, f = i & 127;
    s.Kt[c * KSR + f] = kern[f * U_ + n0 + c];
  }
  if (tid < COLS) {
    s.bias_s[tid] = bias[n0 + tid];
    s.wout_s[tid] = wout[n0 + tid];
  }
  // stage x_0
  {
    int b = tid >> 5, fq = tid & 31;
    *reinterpret_cast<float4*>(&s.xs[0][b * XSR + fq * 4]) =
        *reinterpret_cast<const float4*>(&x[(b * T_ + 0) * F_ + fq * 4]);
  }
  __syncthreads();

  // u_0 (vectorized: x float4 * transposed-K float4)
  float u = 0.f;
  if (tid < 256) {
    u = s.bias_s[cS];
    const float4* xv = reinterpret_cast<const float4*>(&s.xs[0][bS * XSR]);
    const float4* kv = reinterpret_cast<const float4*>(&s.Kt[cS * KSR]);
    #pragma unroll 8
    for (int j = 0; j < F_ / 4; ++j) {
      float4 a = xv[j], b = kv[j];
      u += a.x * b.x + a.y * b.y + a.z * b.z + a.w * b.w;
    }
  }

  float hval = 0.f;

  for (int t = 0; t < T_; ++t) {
    float dot = 0.f;

    if (t > 0) {
      if (tid == 0) {
        const unsigned tgt = epoch_base + (unsigned)t;
        while ((int)(ld_acq(&g_epoch) - tgt) < 0) {}
      }
      __syncthreads();

      const float4* hsrc = reinterpret_cast<const float4*>(g_h[(t - 1) & 1]);
      float4 pf[4];
      #pragma unroll
      for (int j = 0; j < 4; ++j) pf[j] = ldcg4(hsrc + tid + j * THREADS);

      u64 acc[8];
      #pragma unroll
      for (int j = 0; j < 8; ++j) acc[j] = 0ull;

      const int hOff = kg * 16 + hf * 8;   // thread's base float offset in hs
      const int wOff = kg * 16 + 2 * p;    // thread's base float offset in Ws row-block

      for (int ch = 0; ch < NCHUNK; ++ch) {
        #pragma unroll
        for (int j = 0; j < 4; ++j)
          reinterpret_cast<float4*>(s.hs)[tid + j * THREADS] = pf[j];
        if (ch + 1 < NCHUNK) {
          #pragma unroll
          for (int j = 0; j < 4; ++j)
            pf[j] = ldcg4(hsrc + (ch + 1) * (CHUNK * B_ / 4) + tid + j * THREADS);
        }
        __syncthreads();

        if (ch == 0 && t + 1 < T_) {
          int b = tid >> 5, fq = tid & 31;
          *reinterpret_cast<float4*>(&s.xs[(t + 1) & 1][b * XSR + fq * 4]) =
              *reinterpret_cast<const float4*>(&x[(b * T_ + t + 1) * F_ + fq * 4]);
        }

        const float* hbase = s.hs + hOff;
        const float* wbase = s.Ws + ch * (CHUNK * COLS) + wOff;
        #pragma unroll
        for (int i = 0; i < IPC; ++i) {
          const ulonglong2* hq =
              reinterpret_cast<const ulonglong2*>(hbase + i * 512);
          ulonglong2 h0 = hq[0];
          ulonglong2 h1 = hq[1];
          float2 wv = *reinterpret_cast<const float2*>(wbase + i * 512);
          u64 wa = splat2(wv.x);
          u64 wb = splat2(wv.y);
          fmax2(acc[0], h0.x, wa);
          fmax2(acc[1], h0.y, wa);
          fmax2(acc[2], h1.x, wa);
          fmax2(acc[3], h1.y, wa);
          fmax2(acc[4], h0.x, wb);
          fmax2(acc[5], h0.y, wb);
          fmax2(acc[6], h1.x, wb);
          fmax2(acc[7], h1.y, wb);
        }
        __syncthreads();
      }

      // combine the warp's two k-groups (lane ^ 16 keeps (p,hf))
      #pragma unroll
      for (int j = 0; j < 8; ++j)
        acc[j] = addx2(acc[j], __shfl_xor_sync(0xFFFFFFFFu, acc[j], 16));

      if (lane < 16) {
        // float layout red[w][c][b], c rows padded to 18
        float* r0 = &s.red[wrp * REDROW + (2 * p) * 18 + hf * 8];
        #pragma unroll
        for (int q = 0; q < 4; ++q) *reinterpret_cast<u64*>(r0 + 2 * q) = acc[q];
        float* r1 = r0 + 18;
        #pragma unroll
        for (int q = 0; q < 4; ++q) *reinterpret_cast<u64*>(r1 + 2 * q) = acc[4 + q];
      }
      __syncthreads();

      if (tid < 256) {
        float sum = 0.f;
        const float* rp = &s.red[cS * 18 + bS];
        #pragma unroll
        for (int g = 0; g < 16; ++g) sum += rp[g * REDROW];
        dot = sum;
      }
    } else {
      // t == 0: stage x_1
      int b = tid >> 5, fq = tid & 31;
      *reinterpret_cast<float4*>(&s.xs[1][b * XSR + fq * 4]) =
          *reinterpret_cast<const float4*>(&x[(b * T_ + 1) * F_ + fq * 4]);
    }

    // ---- state update ----
    if (tid < 256) {
      hval = tanhf(u + dot);
      g_h[t & 1][(n0 + cS) * B_ + bS] = hval;
    }
    __syncthreads();  // all h stores + red reads done before arrive
    if (tid == 0) {
      if (atom_arrive(&g_arrive) == GRID - 1) {
        g_arrive = 0;
        st_rel(&g_epoch, epoch_base + (unsigned)t + 1u);
      }
    }

    // ---- u_{t+1} while other CTAs arrive ----
    if (t + 1 < T_ && tid < 256) {
      u = s.bias_s[cS];
      const float4* xv =
          reinterpret_cast<const float4*>(&s.xs[(t + 1) & 1][bS * XSR]);
      const float4* kv = reinterpret_cast<const float4*>(&s.Kt[cS * KSR]);
      #pragma unroll 8
      for (int j = 0; j < F_ / 4; ++j) {
        float4 a = xv[j], b = kv[j];
        u += a.x * b.x + a.y * b.y + a.z * b.z + a.w * b.w;
      }
    }
  }

  // ---- readout ----
  if (tid < 256) s.ybuf[cS * B_ + bS] = hval * s.wout_s[cS];
  __syncthreads();
  if (tid < B_) {
    float y = 0.f;
    #pragma unroll
    for (int c = 0; c < COLS; ++c) y += s.ybuf[c * B_ + tid];
    atomicAdd(&out[tid], y);
  }
}

extern "C" void kernel_launch(void* const* d_in, const int* in_sizes, int n_in,
                              void* d_out, int out_size) {
  (void)in_sizes; (void)n_in; (void)out_size;
  const float* x    = (const float*)d_in[0];
  const float* kern = (const float*)d_in[1];
  const float* W    = (const float*)d_in[2];
  const float* bias = (const float*)d_in[3];
  const float* wout = (const float*)d_in[4];
  const float* bout = (const float*)d_in[5];

  cudaFuncSetAttribute(esn_kernel, cudaFuncAttributeMaxDynamicSharedMemorySize,
                       (int)sizeof(SmemLayout));
  esn_kernel<<<GRID, THREADS, sizeof(SmemLayout)>>>(
      x, kern, W, bias, wout, bout, (float*)d_out);
}